// round 1
// baseline (speedup 1.0000x reference)
#include <cuda_runtime.h>

// VectorQuantizer: x (B,) int32 indices, W (K, D) fp32 codebook.
// Since x_emb = W[x], argmin_k ||W[x_i]-W[k]||^2 == x_i (rows distinct, min
// inter-row distance ~2.5 >> fp noise). Therefore:
//   quantized = W[x], diff = 0, loss = 0.25 * sum(W^2).
// Output layout (flattened tuple): [loss, quantized(B*D), diff(B*D)].

#define NUM_K   8192
#define DIM     512
#define BATCH   16384
#define WSIZE   (NUM_K * DIM)        // 4194304 floats
#define BD      (BATCH * DIM)        // 8388608 floats

#define RBLOCKS 512
#define RTHREADS 256

__device__ float g_partials[RBLOCKS];

// Pass 1: per-block partial sums of W^2 (deterministic fixed-tree reduce).
__global__ void vq_sumsq_kernel(const float4* __restrict__ W4) {
    const int n4 = WSIZE / 4;
    float acc = 0.0f;
    for (int i = blockIdx.x * blockDim.x + threadIdx.x; i < n4;
         i += gridDim.x * blockDim.x) {
        float4 v = W4[i];
        acc += v.x * v.x + v.y * v.y + v.z * v.z + v.w * v.w;
    }
    __shared__ float s[RTHREADS];
    s[threadIdx.x] = acc;
    __syncthreads();
    #pragma unroll
    for (int o = RTHREADS / 2; o > 0; o >>= 1) {
        if (threadIdx.x < o) s[threadIdx.x] += s[threadIdx.x + o];
        __syncthreads();
    }
    if (threadIdx.x == 0) g_partials[blockIdx.x] = s[0];
}

// Pass 2: single block folds the partials in fixed order; writes loss.
__global__ void vq_finalize_kernel(float* __restrict__ out) {
    __shared__ float s[RBLOCKS];
    // RBLOCKS == 512, blockDim == 256: each thread loads 2
    s[threadIdx.x]            = g_partials[threadIdx.x];
    s[threadIdx.x + RTHREADS] = g_partials[threadIdx.x + RTHREADS];
    __syncthreads();
    #pragma unroll
    for (int o = RBLOCKS / 2; o > 0; o >>= 1) {
        if (threadIdx.x < o) s[threadIdx.x] += s[threadIdx.x + o];
        __syncthreads();
    }
    if (threadIdx.x == 0) out[0] = 0.25f * s[0];
}

// Gather quantized = W[x] and zero diff. Output region starts at +1 element
// (4B-aligned only), so stores are scalar; loads are aligned float4.
__global__ void vq_gather_kernel(const int* __restrict__ x,
                                 const float* __restrict__ W,
                                 float* __restrict__ out) {
    int i4 = blockIdx.x * blockDim.x + threadIdx.x;   // float4 idx in quantized
    if (i4 >= BD / 4) return;
    int b  = i4 >> 7;          // / (DIM/4)
    int d4 = i4 & 127;
    int row = __ldg(&x[b]);
    float4 v = reinterpret_cast<const float4*>(W)[(size_t)row * (DIM / 4) + d4];

    float* q = out + 1 + (size_t)i4 * 4;
    q[0] = v.x; q[1] = v.y; q[2] = v.z; q[3] = v.w;

    float* df = out + 1 + (size_t)BD + (size_t)i4 * 4;
    df[0] = 0.0f; df[1] = 0.0f; df[2] = 0.0f; df[3] = 0.0f;
}

extern "C" void kernel_launch(void* const* d_in, const int* in_sizes, int n_in,
                              void* d_out, int out_size) {
    // Identify inputs by size (robust to metadata ordering).
    const int*   x = nullptr;
    const float* W = nullptr;
    if (in_sizes[0] == BATCH) {
        x = (const int*)d_in[0];
        W = (const float*)d_in[1];
    } else {
        W = (const float*)d_in[0];
        x = (const int*)d_in[1];
    }
    float* out = (float*)d_out;

    vq_sumsq_kernel<<<RBLOCKS, RTHREADS>>>((const float4*)W);
    vq_finalize_kernel<<<1, RTHREADS>>>(out);

    const int threads = 256;
    const int blocks  = (BD / 4 + threads - 1) / threads;  // 8192
    vq_gather_kernel<<<blocks, threads>>>(x, W, out);
}

// round 2
// speedup vs baseline: 1.5448x; 1.5448x over previous
#include <cuda_runtime.h>

// VectorQuantizer: x (B,) int32 indices, W (K, D) fp32 codebook.
// x_emb = W[x]  =>  argmin_k ||W[x_i]-W[k]||^2 == x_i  (rows distinct; min
// inter-row distance ~2.5 >> fp noise in the reference's expansion).
// Therefore: quantized = W[x], diff = 0, loss = 0.25 * sum(W^2).
// Output layout (flattened tuple): [loss, quantized(B*D), diff(B*D)].
//
// Single fused kernel:
//   blocks [0, SUMB)              : sum(W^2) partials; last-arriving block
//                                   folds partials (fixed order) -> out[0]
//   blocks [SUMB, SUMB+QBLK)      : quantized gather, STG.128 to out+4+4t
//   blocks [SUMB+QBLK, ...)       : zero-fill diff, STG.128
// Scalar head/tail elements (misaligned edges) handled by one thread.

#define NUM_K   8192
#define DIM     512
#define BATCH   16384
#define WSIZE   (NUM_K * DIM)          // 4194304 floats
#define BD      (BATCH * DIM)          // 8388608 floats

#define THREADS 256
#define SUMB    1024                   // 1024*256*4 float4 = WSIZE/4 exactly
#define QVEC    2097151                // float4 chunks covering out[4..8388608)
#define ZVEC    2097151                // float4 chunks covering out[8388612..16777216)
#define QBLK    8192
#define ZBLK    8192
#define GRID    (SUMB + QBLK + ZBLK)

__device__ float        g_partials[SUMB];
__device__ unsigned int g_count = 0;   // self-resetting ticket (graph-replay safe)

__global__ void __launch_bounds__(THREADS)
vq_fused_kernel(const int* __restrict__ x,
                const float* __restrict__ W,
                float* __restrict__ out) {
    const int blk = blockIdx.x;
    const int tid = threadIdx.x;

    if (blk < SUMB) {
        // ---- sum of squares over W, 4 front-batched float4 loads (MLP=4) ----
        const float4* W4 = reinterpret_cast<const float4*>(W);
        size_t base = (size_t)blk * (THREADS * 4) + tid;
        float4 a = W4[base];
        float4 b = W4[base + THREADS];
        float4 c = W4[base + 2 * THREADS];
        float4 d = W4[base + 3 * THREADS];
        float acc = a.x * a.x + a.y * a.y + a.z * a.z + a.w * a.w;
        acc      += b.x * b.x + b.y * b.y + b.z * b.z + b.w * b.w;
        acc      += c.x * c.x + c.y * c.y + c.z * c.z + c.w * c.w;
        acc      += d.x * d.x + d.y * d.y + d.z * d.z + d.w * d.w;

        __shared__ float s[THREADS];
        s[tid] = acc;
        __syncthreads();
        #pragma unroll
        for (int o = THREADS / 2; o > 0; o >>= 1) {
            if (tid < o) s[tid] += s[tid + o];
            __syncthreads();
        }

        __shared__ bool s_last;
        if (tid == 0) {
            g_partials[blk] = s[0];
            __threadfence();
            unsigned int old = atomicAdd(&g_count, 1u);
            s_last = (old == SUMB - 1);
        }
        __syncthreads();

        if (s_last) {
            // fold all partials in fixed order (deterministic), bypass L1
            float p = __ldcg(&g_partials[tid])
                    + __ldcg(&g_partials[tid + 256])
                    + __ldcg(&g_partials[tid + 512])
                    + __ldcg(&g_partials[tid + 768]);
            s[tid] = p;
            __syncthreads();
            #pragma unroll
            for (int o = THREADS / 2; o > 0; o >>= 1) {
                if (tid < o) s[tid] += s[tid + o];
                __syncthreads();
            }
            if (tid == 0) {
                out[0] = 0.25f * s[0];
                g_count = 0;           // reset for next graph replay
            }
        }
    } else if (blk < SUMB + QBLK) {
        // ---- quantized gather: float4 chunk t covers out[4+4t .. 8+4t) ----
        int t = (blk - SUMB) * THREADS + tid;
        if (t < QVEC) {
            int j0  = 3 + 4 * t;               // source element index
            int b   = j0 >> 9;
            int d   = j0 & 511;
            int row = __ldg(&x[b]);
            const float* src = W + ((size_t)row << 9) + d;
            float4 v;
            if (d != 511) {
                v.x = __ldg(src);
                v.y = __ldg(src + 1);
                v.z = __ldg(src + 2);
                v.w = __ldg(src + 3);
            } else {                           // chunk straddles a row boundary
                v.x = __ldg(src);
                int row2 = __ldg(&x[b + 1]);
                const float* s2 = W + ((size_t)row2 << 9);
                v.y = __ldg(s2);
                v.z = __ldg(s2 + 1);
                v.w = __ldg(s2 + 2);
            }
            *reinterpret_cast<float4*>(out + 4 + (size_t)4 * t) = v;
        }
        if (blk == SUMB && tid == 0) {
            // scalar edges
            int r0 = __ldg(&x[0]);
            const float* s0 = W + ((size_t)r0 << 9);
            out[1] = __ldg(s0);
            out[2] = __ldg(s0 + 1);
            out[3] = __ldg(s0 + 2);
            int rl = __ldg(&x[BATCH - 1]);
            out[1 + (size_t)BD - 1] = __ldg(W + ((size_t)rl << 9) + 511); // j=BD-1
            // diff scalar edges
            out[(size_t)1 + BD]     = 0.0f;
            out[(size_t)2 + BD]     = 0.0f;
            out[(size_t)3 + BD]     = 0.0f;
            out[(size_t)2 * BD]     = 0.0f;    // index 16777216
        }
    } else {
        // ---- diff zero-fill: float4 chunk t covers out[8388612+4t ..) ----
        int t = (blk - SUMB - QBLK) * THREADS + tid;
        if (t < ZVEC) {
            float4 z = make_float4(0.f, 0.f, 0.f, 0.f);
            *reinterpret_cast<float4*>(out + (size_t)4 + BD + (size_t)4 * t) = z;
        }
    }
}

extern "C" void kernel_launch(void* const* d_in, const int* in_sizes, int n_in,
                              void* d_out, int out_size) {
    const int*   x = nullptr;
    const float* W = nullptr;
    if (in_sizes[0] == BATCH) {
        x = (const int*)d_in[0];
        W = (const float*)d_in[1];
    } else {
        W = (const float*)d_in[0];
        x = (const int*)d_in[1];
    }
    float* out = (float*)d_out;
    vq_fused_kernel<<<GRID, THREADS>>>(x, W, out);
}

// round 3
// speedup vs baseline: 1.7065x; 1.1047x over previous
#include <cuda_runtime.h>

// VectorQuantizer: x (B,) int32 indices, W (K, D) fp32 codebook.
// x_emb = W[x]  =>  argmin_k ||W[x_i]-W[k]||^2 == x_i  (rows distinct; min
// inter-row distance ~2.5 >> fp noise). Therefore:
//   quantized = W[x], diff = 0, loss = 0.25 * sum(W^2).
// Output layout: [loss, quantized(B*D), diff(B*D)]  (out_size = 1 + 2*B*D).
//
// One fused kernel, three block ranges:
//   [0, SUMB)              sum(W^2); last-arriving block folds -> out[0]
//   [SUMB, SUMB+QBLK)      gather: warp-per-row, LDG.128 + SHFL realign + STG.128
//   [SUMB+QBLK, GRID)      zero-fill diff with STG.128, 8 chunks/thread

#define NUM_K   8192
#define DIM     512
#define BATCH   16384
#define WSIZE   (NUM_K * DIM)          // 4194304 floats
#define BD      (BATCH * DIM)          // 8388608 floats

#define THREADS 256
#define SUMB    512                    // 512*256*8 float4 = WSIZE/4
#define QBLK    (BATCH / 8)            // 8 warps/block, 1 row/warp -> 2048
#define ZVEC    ((BD - 4) / 4)         // 2097151 float4 chunks for diff
#define ZBLK    1024                   // 1024*256 threads * 8 chunks >= ZVEC
#define GRID    (SUMB + QBLK + ZBLK)

__device__ float        g_partials[SUMB];
__device__ unsigned int g_count = 0;   // self-resetting ticket (graph-replay safe)

__global__ void __launch_bounds__(THREADS)
vq_fused_kernel(const int* __restrict__ x,
                const float* __restrict__ W,
                float* __restrict__ out) {
    const int blk = blockIdx.x;
    const int tid = threadIdx.x;

    if (blk < SUMB) {
        // ---- sum of squares over W: 8 front-batched float4 loads ----
        const float4* W4 = reinterpret_cast<const float4*>(W);
        size_t base = (size_t)blk * (THREADS * 8) + tid;
        float acc = 0.0f;
        #pragma unroll
        for (int i = 0; i < 8; ++i) {
            float4 v = W4[base + (size_t)i * THREADS];
            acc += v.x * v.x + v.y * v.y + v.z * v.z + v.w * v.w;
        }

        __shared__ float s[THREADS];
        s[tid] = acc;
        __syncthreads();
        #pragma unroll
        for (int o = THREADS / 2; o > 0; o >>= 1) {
            if (tid < o) s[tid] += s[tid + o];
            __syncthreads();
        }

        __shared__ bool s_last;
        if (tid == 0) {
            g_partials[blk] = s[0];
            __threadfence();
            s_last = (atomicAdd(&g_count, 1u) == SUMB - 1);
        }
        __syncthreads();

        if (s_last) {
            float p = __ldcg(&g_partials[tid]) + __ldcg(&g_partials[tid + 256]);
            s[tid] = p;
            __syncthreads();
            #pragma unroll
            for (int o = THREADS / 2; o > 0; o >>= 1) {
                if (tid < o) s[tid] += s[tid + o];
                __syncthreads();
            }
            if (tid == 0) {
                out[0] = 0.25f * s[0];
                g_count = 0;           // reset for next graph replay
            }
        }
    } else if (blk < SUMB + QBLK) {
        // ---- gather quantized = W[x]: one warp per batch row ----
        const unsigned FULL = 0xffffffffu;
        const int wid = tid >> 5;
        const int lid = tid & 31;
        const int b   = (blk - SUMB) * 8 + wid;          // batch row

        int row = 0;
        if (lid == 0) row = __ldg(&x[b]);
        row = __shfl_sync(FULL, row, 0);

        const float*  src  = W + ((size_t)row << 9);
        const float4* src4 = reinterpret_cast<const float4*>(src);
        float*        dst  = out + 1 + ((size_t)b << 9);

        // carry = src[3] = src4[0].w, needed by lane 0 of iteration 0
        float carry = 0.0f;
        if (lid == 0) carry = __ldg(src + 3);

        // 127 aligned output chunks: dst[3+4k .. 7+4k) = (src4[k].w, src4[k+1].xyz)
        #pragma unroll
        for (int it = 0; it < 4; ++it) {
            int  k     = it * 32 + lid;
            int  kc    = (k < 127) ? k : 126;            // clamp OOB lane
            float4 A   = src4[kc + 1];                   // aligned LDG.128
            float wprev = __shfl_up_sync(FULL, A.w, 1);
            float vx    = (lid == 0) ? carry : wprev;
            if (k < 127) {
                float4 v = make_float4(vx, A.x, A.y, A.z);
                *reinterpret_cast<float4*>(dst + 3 + 4 * k) = v;  // aligned STG.128
            }
            carry = __shfl_sync(FULL, A.w, 31);          // src4[(it+1)*32].w
        }

        // edges: dst[0..2] = src[0..2], dst[511] = src[511]
        if (lid < 3)       dst[lid] = __ldg(src + lid);
        else if (lid == 3) dst[511] = __ldg(src + 511);

        // global scalar edges of the diff region (done once)
        if (blk == SUMB && wid == 0 && lid < 4) {
            size_t idx = (lid < 3) ? ((size_t)BD + 1 + lid) : (size_t)2 * BD;
            out[idx] = 0.0f;
        }
    } else {
        // ---- diff zero-fill: float4 chunks from out+4+BD, 8 per thread ----
        float4 z = make_float4(0.f, 0.f, 0.f, 0.f);
        int t0 = (blk - SUMB - QBLK) * THREADS + tid;
        float* zbase = out + 4 + (size_t)BD;
        #pragma unroll
        for (int i = 0; i < 8; ++i) {
            int t = t0 + i * (ZBLK * THREADS);
            if (t < ZVEC)
                *reinterpret_cast<float4*>(zbase + (size_t)4 * t) = z;
        }
    }
}

extern "C" void kernel_launch(void* const* d_in, const int* in_sizes, int n_in,
                              void* d_out, int out_size) {
    const int*   x = nullptr;
    const float* W = nullptr;
    if (in_sizes[0] == BATCH) {
        x = (const int*)d_in[0];
        W = (const float*)d_in[1];
    } else {
        W = (const float*)d_in[0];
        x = (const int*)d_in[1];
    }
    float* out = (float*)d_out;
    vq_fused_kernel<<<GRID, THREADS>>>(x, W, out);
}